// round 5
// baseline (speedup 1.0000x reference)
#include <cuda_runtime.h>
#include <cuda_fp16.h>
#include <cstdint>

// SeparableConv fused, round 5:
//  - depthwise: thread = (4 channels x 1 pixel-column), float4 streaming window,
//    30 LDG.128 + 16 STS.64 per thread (was 80 LDG.32 + 64 STS.16)
//  - A[2][64][136]f16 + B[256][136]f16 in smem (103KB -> 2 CTAs/SM)
//  - mma.sync m16n8k16 hi/lo fp16 split, B frags reused across splits
//  - B column-permuted -> contiguous float4 epilogue

#define IMG_H 112
#define IMG_W 112
#define CIN   128
#define COUT  256
#define NIMG  32
#define TILES_X 14
#define TILES_Y 14
#define NTILES (NIMG * TILES_X * TILES_Y)   // 6272
#define GRID  296

#define SM_B    0
#define SM_BIAS 69632
#define SM_A    70656
#define SM_BYTES 105472

#define A_ROW_B   272
#define A_SPLIT_B 17408
#define B_ROW_B   272

extern __shared__ unsigned char smem[];

__device__ __forceinline__ uint32_t smem_u32(const void* p) {
    uint32_t a;
    asm("{ .reg .u64 t; cvta.to.shared.u64 t, %1; cvt.u32.u64 %0, t; }" : "=r"(a) : "l"(p));
    return a;
}
__device__ __forceinline__ void ldsm_x4(uint32_t* r, uint32_t addr) {
    asm volatile("ldmatrix.sync.aligned.m8n8.x4.shared.b16 {%0,%1,%2,%3}, [%4];"
                 : "=r"(r[0]), "=r"(r[1]), "=r"(r[2]), "=r"(r[3]) : "r"(addr));
}
__device__ __forceinline__ void mma16816(float* d, const uint32_t* a,
                                         const uint32_t* b, const float* c) {
    asm volatile(
        "mma.sync.aligned.m16n8k16.row.col.f32.f16.f16.f32 "
        "{%0,%1,%2,%3}, {%4,%5,%6,%7}, {%8,%9}, {%10,%11,%12,%13};"
        : "=f"(d[0]), "=f"(d[1]), "=f"(d[2]), "=f"(d[3])
        : "r"(a[0]), "r"(a[1]), "r"(a[2]), "r"(a[3]),
          "r"(b[0]), "r"(b[1]),
          "f"(c[0]), "f"(c[1]), "f"(c[2]), "f"(c[3]));
}
__device__ __forceinline__ float4 fma4(float4 a, float4 b, float4 c) {
    c.x = fmaf(a.x, b.x, c.x); c.y = fmaf(a.y, b.y, c.y);
    c.z = fmaf(a.z, b.z, c.z); c.w = fmaf(a.w, b.w, c.w);
    return c;
}

__global__ __launch_bounds__(256, 2)
void sepconv_mma_kernel(const float* __restrict__ x,
                        const float* __restrict__ dwk,
                        const float* __restrict__ dwb,
                        const float* __restrict__ pwk,
                        const float* __restrict__ pwb,
                        float* __restrict__ out) {
    const int tid  = threadIdx.x;
    const int lane = tid & 31;
    const int wid  = tid >> 5;

    const uint32_t s0  = smem_u32(smem);
    const uint32_t A_a = s0 + SM_A;
    const uint32_t B_a = s0 + SM_B;

    __half* Bs   = (__half*)(smem + SM_B);
    float*  bias = (float*)(smem + SM_BIAS);
    unsigned char* Asm = smem + SM_A;

    // ---- prologue: bias + permuted B(fp16) ----
    for (int i = tid; i < COUT; i += 256) bias[i] = pwb[i];
    for (int i = tid; i < CIN * COUT; i += 256) {
        int k = i >> 8;
        int n = i & 255;
        int seg = n & 192;
        int q   = n & 63;
        int row = seg + ((q & 15) >> 1) * 8 + (q >> 4) * 2 + (q & 1);
        Bs[row * 136 + k] = __float2half_rn(pwk[k * 256 + n]);
    }

    // dw params: thread owns channels 4*c4..4*c4+3, pixel column px
    const int c4 = lane;        // 0..31
    const int px = wid;         // 0..7
    float4 w4[9];
    #pragma unroll
    for (int t = 0; t < 9; t++) w4[t] = *(const float4*)(dwk + t * CIN + c4 * 4);
    const float4 b4 = *(const float4*)(dwb + c4 * 4);
    __syncthreads();

    // MMA warp tiling: 2 (M) x 4 (N), warp tile 32 x 64
    const int wm = wid >> 2, wn = wid & 3;
    const int m0 = wm * 32;
    const int n0 = wn * 64;
    const int g  = lane & 3;
    const int rr = lane >> 2;

    const uint32_t addrA0 = A_a + (uint32_t)(m0 + (lane & 15)) * A_ROW_B + (lane & 16);
    const uint32_t addrB0 = B_a + (uint32_t)(n0 + (lane & 7) + ((lane & 16) >> 1)) * B_ROW_B
                                + ((lane & 8) << 1);

    const uint32_t a_off = (uint32_t)c4 * 8;   // channel byte offset in A row

    for (int t = blockIdx.x; t < NTILES; t += GRID) {
        int n   = t / (TILES_X * TILES_Y);
        int rem = t - n * (TILES_X * TILES_Y);
        int by  = rem / TILES_X;
        int bx  = rem - by * TILES_X;
        int ty0 = by * 8, tx0 = bx * 8;

        __syncthreads();   // previous tile's ldsm reads of A complete

        // ======== depthwise: stream 10 rows of a 3-col float4 window ========
        {
            const float* xp = x + (size_t)n * (IMG_H * IMG_W * CIN) + c4 * 4;
            const int gxb = tx0 + px - 1;
            float4 win[3][3];
            #pragma unroll
            for (int r = 0; r < 10; r++) {
                const int gy = ty0 - 1 + r;
                const bool oky = (unsigned)gy < IMG_H;
                #pragma unroll
                for (int dj = 0; dj < 3; dj++) {
                    const int gx = gxb + dj;
                    float4 v = make_float4(0.f, 0.f, 0.f, 0.f);
                    if (oky && ((unsigned)gx < IMG_W))
                        v = *(const float4*)(xp + ((size_t)(gy * IMG_W + gx)) * CIN);
                    win[r % 3][dj] = v;
                }
                if (r >= 2) {
                    float4 y = b4;
                    #pragma unroll
                    for (int di = 0; di < 3; di++) {
                        const float4* rw = win[(r - 2 + di) % 3];
                        #pragma unroll
                        for (int dj = 0; dj < 3; dj++)
                            y = fma4(w4[di * 3 + dj], rw[dj], y);
                    }
                    __half2 h01 = __floats2half2_rn(y.x, y.y);
                    __half2 h23 = __floats2half2_rn(y.z, y.w);
                    __half2 l01 = __floats2half2_rn(y.x - __low2float(h01),
                                                    y.y - __high2float(h01));
                    __half2 l23 = __floats2half2_rn(y.z - __low2float(h23),
                                                    y.w - __high2float(h23));
                    const int p = (r - 2) * 8 + px;
                    uint32_t off = (uint32_t)p * A_ROW_B + a_off;
                    *(uint2*)(Asm + off) =
                        make_uint2(*(uint32_t*)&h01, *(uint32_t*)&h23);
                    *(uint2*)(Asm + A_SPLIT_B + off) =
                        make_uint2(*(uint32_t*)&l01, *(uint32_t*)&l23);
                }
            }
        }
        __syncthreads();   // A ready

        // ======== MMA ========
        float acc[2][8][4];
        #pragma unroll
        for (int mi = 0; mi < 2; mi++)
            #pragma unroll
            for (int nj = 0; nj < 8; nj++)
                #pragma unroll
                for (int q = 0; q < 4; q++) acc[mi][nj][q] = 0.0f;

        #pragma unroll
        for (int kk = 0; kk < 8; kk++) {
            uint32_t aB = addrB0 + (uint32_t)kk * 32;
            uint32_t bfr[4][4];
            #pragma unroll
            for (int j = 0; j < 4; j++) ldsm_x4(bfr[j], aB + (uint32_t)j * 16 * B_ROW_B);
            #pragma unroll
            for (int s = 0; s < 2; s++) {
                uint32_t aA = addrA0 + (uint32_t)s * A_SPLIT_B + (uint32_t)kk * 32;
                uint32_t afr[2][4];
                ldsm_x4(afr[0], aA);
                ldsm_x4(afr[1], aA + 16 * A_ROW_B);
                #pragma unroll
                for (int j = 0; j < 4; j++) {
                    mma16816(acc[0][2*j],   afr[0], &bfr[j][0], acc[0][2*j]);
                    mma16816(acc[0][2*j+1], afr[0], &bfr[j][2], acc[0][2*j+1]);
                    mma16816(acc[1][2*j],   afr[1], &bfr[j][0], acc[1][2*j]);
                    mma16816(acc[1][2*j+1], afr[1], &bfr[j][2], acc[1][2*j+1]);
                }
            }
        }

        // ======== epilogue (contiguous float4, permuted cols) ========
        #pragma unroll
        for (int mi = 0; mi < 2; mi++) {
            int r0 = m0 + mi * 16 + rr;
            int r1 = r0 + 8;
            float* o0 = out + ((size_t)((n * IMG_H + ty0 + (r0 >> 3)) * IMG_W)
                               + tx0 + (r0 & 7)) * COUT + n0 + g * 16;
            float* o1 = out + ((size_t)((n * IMG_H + ty0 + (r1 >> 3)) * IMG_W)
                               + tx0 + (r1 & 7)) * COUT + n0 + g * 16;
            #pragma unroll
            for (int k = 0; k < 4; k++) {
                float4 bv = *(const float4*)(bias + n0 + g * 16 + k * 4);
                float4 v0, v1;
                v0.x = acc[mi][2*k][0]   + bv.x;
                v0.y = acc[mi][2*k][1]   + bv.y;
                v0.z = acc[mi][2*k+1][0] + bv.z;
                v0.w = acc[mi][2*k+1][1] + bv.w;
                v1.x = acc[mi][2*k][2]   + bv.x;
                v1.y = acc[mi][2*k][3]   + bv.y;
                v1.z = acc[mi][2*k+1][2] + bv.z;
                v1.w = acc[mi][2*k+1][3] + bv.w;
                *(float4*)(o0 + k * 4) = v0;
                *(float4*)(o1 + k * 4) = v1;
            }
        }
    }
}

extern "C" void kernel_launch(void* const* d_in, const int* in_sizes, int n_in,
                              void* d_out, int out_size) {
    const float* x   = (const float*)d_in[0];
    const float* dwk = (const float*)d_in[1];
    const float* dwb = (const float*)d_in[2];
    const float* pwk = (const float*)d_in[3];
    const float* pwb = (const float*)d_in[4];
    float* out = (float*)d_out;

    static bool init = false;
    if (!init) {
        cudaFuncSetAttribute(sepconv_mma_kernel,
                             cudaFuncAttributeMaxDynamicSharedMemorySize, SM_BYTES);
        init = true;
    }
    sepconv_mma_kernel<<<GRID, 256, SM_BYTES>>>(x, dwk, dwb, pwk, pwb, out);
}

// round 6
// speedup vs baseline: 1.1616x; 1.1616x over previous
#include <cuda_runtime.h>
#include <cuda_fp16.h>
#include <cstdint>

// SeparableConv fused, round 6:
//  - single fp16 pass (A fp16 * W fp16, fp32 accum): halves MMA/ldsm/STS vs r5
//  - A double-buffered -> ONE __syncthreads per tile (pipeline across tiles)
//  - depthwise: thread = (4ch x 1col) float4 streaming window from global
//  - B column-permuted -> contiguous float4 epilogue. 2 CTAs/SM.

#define IMG_H 112
#define IMG_W 112
#define CIN   128
#define COUT  256
#define NIMG  32
#define TILES_X 14
#define TILES_Y 14
#define NTILES (NIMG * TILES_X * TILES_Y)   // 6272
#define GRID  296

// smem: B[256][136]f16 69632 | bias 1024 | A x2 [64][136]f16 17408 each
#define SM_B    0
#define SM_BIAS 69632
#define SM_A    70656
#define A_BUF_B 17408
#define SM_BYTES 105472

#define A_ROW_B   272
#define B_ROW_B   272

extern __shared__ unsigned char smem[];

__device__ __forceinline__ uint32_t smem_u32(const void* p) {
    uint32_t a;
    asm("{ .reg .u64 t; cvta.to.shared.u64 t, %1; cvt.u32.u64 %0, t; }" : "=r"(a) : "l"(p));
    return a;
}
__device__ __forceinline__ void ldsm_x4(uint32_t* r, uint32_t addr) {
    asm volatile("ldmatrix.sync.aligned.m8n8.x4.shared.b16 {%0,%1,%2,%3}, [%4];"
                 : "=r"(r[0]), "=r"(r[1]), "=r"(r[2]), "=r"(r[3]) : "r"(addr));
}
__device__ __forceinline__ void mma16816(float* d, const uint32_t* a,
                                         const uint32_t* b, const float* c) {
    asm volatile(
        "mma.sync.aligned.m16n8k16.row.col.f32.f16.f16.f32 "
        "{%0,%1,%2,%3}, {%4,%5,%6,%7}, {%8,%9}, {%10,%11,%12,%13};"
        : "=f"(d[0]), "=f"(d[1]), "=f"(d[2]), "=f"(d[3])
        : "r"(a[0]), "r"(a[1]), "r"(a[2]), "r"(a[3]),
          "r"(b[0]), "r"(b[1]),
          "f"(c[0]), "f"(c[1]), "f"(c[2]), "f"(c[3]));
}
__device__ __forceinline__ float4 fma4(float4 a, float4 b, float4 c) {
    c.x = fmaf(a.x, b.x, c.x); c.y = fmaf(a.y, b.y, c.y);
    c.z = fmaf(a.z, b.z, c.z); c.w = fmaf(a.w, b.w, c.w);
    return c;
}

__global__ __launch_bounds__(256, 2)
void sepconv_mma_kernel(const float* __restrict__ x,
                        const float* __restrict__ dwk,
                        const float* __restrict__ dwb,
                        const float* __restrict__ pwk,
                        const float* __restrict__ pwb,
                        float* __restrict__ out) {
    const int tid  = threadIdx.x;
    const int lane = tid & 31;
    const int wid  = tid >> 5;

    const uint32_t s0  = smem_u32(smem);
    const uint32_t A_a = s0 + SM_A;
    const uint32_t B_a = s0 + SM_B;

    __half* Bs   = (__half*)(smem + SM_B);
    float*  bias = (float*)(smem + SM_BIAS);
    unsigned char* Asm = smem + SM_A;

    // ---- prologue: bias + permuted B(fp16) ----
    for (int i = tid; i < COUT; i += 256) bias[i] = pwb[i];
    for (int i = tid; i < CIN * COUT; i += 256) {
        int k = i >> 8;
        int n = i & 255;
        int seg = n & 192;
        int q   = n & 63;
        int row = seg + ((q & 15) >> 1) * 8 + (q >> 4) * 2 + (q & 1);
        Bs[row * 136 + k] = __float2half_rn(pwk[k * 256 + n]);
    }

    // dw params: thread owns channels 4*c4..4*c4+3, pixel column px
    const int c4 = lane;
    const int px = wid;
    float4 w4[9];
    #pragma unroll
    for (int t = 0; t < 9; t++) w4[t] = *(const float4*)(dwk + t * CIN + c4 * 4);
    const float4 b4 = *(const float4*)(dwb + c4 * 4);
    __syncthreads();

    // MMA warp tiling: 2 (M) x 4 (N), warp tile 32 x 64
    const int wm = wid >> 2, wn = wid & 3;
    const int m0 = wm * 32;
    const int n0 = wn * 64;
    const int g  = lane & 3;
    const int rr = lane >> 2;

    const uint32_t addrA0 = A_a + (uint32_t)(m0 + (lane & 15)) * A_ROW_B + (lane & 16);
    const uint32_t addrB0 = B_a + (uint32_t)(n0 + (lane & 7) + ((lane & 16) >> 1)) * B_ROW_B
                                + ((lane & 8) << 1);

    const uint32_t a_off = (uint32_t)c4 * 8;
    uint32_t buf = 0;

    for (int t = blockIdx.x; t < NTILES; t += GRID) {
        int n   = t / (TILES_X * TILES_Y);
        int rem = t - n * (TILES_X * TILES_Y);
        int by  = rem / TILES_X;
        int bx  = rem - by * TILES_X;
        int ty0 = by * 8, tx0 = bx * 8;

        // ======== depthwise into A[buf] (no barrier needed before: buffer
        //          parity + the single per-tile barrier guarantee safety) ====
        {
            const float* xp = x + (size_t)n * (IMG_H * IMG_W * CIN) + c4 * 4;
            const int gxb = tx0 + px - 1;
            unsigned char* Ab = Asm + buf * A_BUF_B;
            float4 win[3][3];
            #pragma unroll
            for (int r = 0; r < 10; r++) {
                const int gy = ty0 - 1 + r;
                const bool oky = (unsigned)gy < IMG_H;
                #pragma unroll
                for (int dj = 0; dj < 3; dj++) {
                    const int gx = gxb + dj;
                    float4 v = make_float4(0.f, 0.f, 0.f, 0.f);
                    if (oky && ((unsigned)gx < IMG_W))
                        v = *(const float4*)(xp + ((size_t)(gy * IMG_W + gx)) * CIN);
                    win[r % 3][dj] = v;
                }
                if (r >= 2) {
                    float4 y = b4;
                    #pragma unroll
                    for (int di = 0; di < 3; di++) {
                        const float4* rw = win[(r - 2 + di) % 3];
                        #pragma unroll
                        for (int dj = 0; dj < 3; dj++)
                            y = fma4(w4[di * 3 + dj], rw[dj], y);
                    }
                    __half2 h01 = __floats2half2_rn(y.x, y.y);
                    __half2 h23 = __floats2half2_rn(y.z, y.w);
                    const int p = (r - 2) * 8 + px;
                    *(uint2*)(Ab + (uint32_t)p * A_ROW_B + a_off) =
                        make_uint2(*(uint32_t*)&h01, *(uint32_t*)&h23);
                }
            }
        }
        __syncthreads();   // A[buf] complete; also fences prev-tile A reads

        // ======== MMA (single fp16 pass) ========
        float acc[2][8][4];
        #pragma unroll
        for (int mi = 0; mi < 2; mi++)
            #pragma unroll
            for (int nj = 0; nj < 8; nj++)
                #pragma unroll
                for (int q = 0; q < 4; q++) acc[mi][nj][q] = 0.0f;

        const uint32_t aAb = addrA0 + buf * A_BUF_B;
        #pragma unroll
        for (int kk = 0; kk < 8; kk++) {
            uint32_t aB = addrB0 + (uint32_t)kk * 32;
            uint32_t bfr[4][4];
            #pragma unroll
            for (int j = 0; j < 4; j++) ldsm_x4(bfr[j], aB + (uint32_t)j * 16 * B_ROW_B);
            uint32_t aA = aAb + (uint32_t)kk * 32;
            uint32_t afr[2][4];
            ldsm_x4(afr[0], aA);
            ldsm_x4(afr[1], aA + 16 * A_ROW_B);
            #pragma unroll
            for (int j = 0; j < 4; j++) {
                mma16816(acc[0][2*j],   afr[0], &bfr[j][0], acc[0][2*j]);
                mma16816(acc[0][2*j+1], afr[0], &bfr[j][2], acc[0][2*j+1]);
                mma16816(acc[1][2*j],   afr[1], &bfr[j][0], acc[1][2*j]);
                mma16816(acc[1][2*j+1], afr[1], &bfr[j][2], acc[1][2*j+1]);
            }
        }

        // ======== epilogue (contiguous float4, permuted cols) ========
        #pragma unroll
        for (int mi = 0; mi < 2; mi++) {
            int r0 = m0 + mi * 16 + rr;
            int r1 = r0 + 8;
            float* o0 = out + ((size_t)((n * IMG_H + ty0 + (r0 >> 3)) * IMG_W)
                               + tx0 + (r0 & 7)) * COUT + n0 + g * 16;
            float* o1 = out + ((size_t)((n * IMG_H + ty0 + (r1 >> 3)) * IMG_W)
                               + tx0 + (r1 & 7)) * COUT + n0 + g * 16;
            #pragma unroll
            for (int k = 0; k < 4; k++) {
                float4 bv = *(const float4*)(bias + n0 + g * 16 + k * 4);
                float4 v0, v1;
                v0.x = acc[mi][2*k][0]   + bv.x;
                v0.y = acc[mi][2*k][1]   + bv.y;
                v0.z = acc[mi][2*k+1][0] + bv.z;
                v0.w = acc[mi][2*k+1][1] + bv.w;
                v1.x = acc[mi][2*k][2]   + bv.x;
                v1.y = acc[mi][2*k][3]   + bv.y;
                v1.z = acc[mi][2*k+1][2] + bv.z;
                v1.w = acc[mi][2*k+1][3] + bv.w;
                *(float4*)(o0 + k * 4) = v0;
                *(float4*)(o1 + k * 4) = v1;
            }
        }

        buf ^= 1;   // next tile writes the other A buffer (no trailing barrier)
    }
}

extern "C" void kernel_launch(void* const* d_in, const int* in_sizes, int n_in,
                              void* d_out, int out_size) {
    const float* x   = (const float*)d_in[0];
    const float* dwk = (const float*)d_in[1];
    const float* dwb = (const float*)d_in[2];
    const float* pwk = (const float*)d_in[3];
    const float* pwb = (const float*)d_in[4];
    float* out = (float*)d_out;

    static bool init = false;
    if (!init) {
        cudaFuncSetAttribute(sepconv_mma_kernel,
                             cudaFuncAttributeMaxDynamicSharedMemorySize, SM_BYTES);
        init = true;
    }
    sepconv_mma_kernel<<<GRID, 256, SM_BYTES>>>(x, dwk, dwb, pwk, pwb, out);
}